// round 6
// baseline (speedup 1.0000x reference)
#include <cuda_runtime.h>
#include <math.h>
#include <stdint.h>

#define T_STEPS 2048
#define BATCH   64
#define IN_DIM  64
#define HID     512
#define O_DIM   32
#define OC_DIM  8

typedef unsigned long long ull;

#define FMA2(acc, a, b) \
    asm("fma.rn.f32x2 %0, %1, %2, %3;" : "=l"(acc) : "l"(a), "l"(b), "l"(acc))

__device__ __forceinline__ uint32_t smem_u32(const void* p) {
    return (uint32_t)__cvta_generic_to_shared(p);
}
__device__ __forceinline__ void cluster_sync_() {
    asm volatile("barrier.cluster.arrive.aligned;" ::: "memory");
    asm volatile("barrier.cluster.wait.aligned;" ::: "memory");
}
__device__ __forceinline__ float hsum2(ull a) {
    float lo, hi;
    asm("mov.b64 {%0, %1}, %2;" : "=f"(lo), "=f"(hi) : "l"(a));
    return lo + hi;
}
__device__ __forceinline__ uint32_t mapa_(uint32_t laddr, uint32_t rank) {
    uint32_t ra;
    asm volatile("mapa.shared::cluster.u32 %0, %1, %2;" : "=r"(ra) : "r"(laddr), "r"(rank));
    return ra;
}
__device__ __forceinline__ void mbar_wait(uint32_t bar, uint32_t par) {
    uint32_t done;
    asm volatile(
        "{\n\t.reg .pred p;\n\t"
        "mbarrier.try_wait.parity.acquire.cluster.shared::cta.b64 p, [%1], %2;\n\t"
        "selp.b32 %0, 1, 0, p;\n\t}"
        : "=r"(done) : "r"(bar), "r"(par) : "memory");
    if (!done) {
        asm volatile(
            "{\n\t.reg .pred P1;\n\t"
            "WL_%=:\n\t"
            "mbarrier.try_wait.parity.acquire.cluster.shared::cta.b64 P1, [%0], %1, 0x989680;\n\t"
            "@P1 bra.uni WD_%=;\n\t"
            "bra.uni WL_%=;\n\t"
            "WD_%=:\n\t}"
            :: "r"(bar), "r"(par) : "memory");
    }
}

// ---------------------------------------------------------------------------
// rnn_kernel: 16 clusters x 8 CTAs x 512 threads.
// CTA rank r: Wh rows [64r,64r+64) in registers (32 ull/thread).
// rate layout [buf][src_rank][batch][64]; comm = per-thread st.async.b32
// scatter (R3-proven) onto PER-SOURCE mbarriers (tx spread over 8 barriers).
// pre[t] computed in-kernel by upper 256 threads overlapped with update.
// ---------------------------------------------------------------------------
struct RnnSmem {
    float rate[2][8][4][64];    // 16 KB  double-buffered rate, src-major
    float part[8][4][64];       //  8 KB  k-partials
    ull   wi[64][33];           // ~17 KB Wi slice (pad 33 for banks)
    ull   xbuf[2][4][32];       //  2 KB  x[t] tile double buffer
    float prebuf[2][4][64];     //  2 KB  pre[t] double buffer
    ull   mbar[2][8];           //  [buf][src]
};

__global__ void __launch_bounds__(512, 1) __cluster_dims__(8, 1, 1)
rnn_kernel(const float* __restrict__ x,
           const float* __restrict__ rate0,
           const float* __restrict__ noise,
           const float* __restrict__ Wi,
           const float* __restrict__ bi,
           const float* __restrict__ Wh,
           const float* __restrict__ bh,
           float* __restrict__ rate_all) {
    extern __shared__ __align__(16) char smem_raw[];
    RnnSmem* s = (RnnSmem*)smem_raw;

    const int tid    = threadIdx.x;
    const int rank   = blockIdx.x & 7;
    const int cid    = blockIdx.x >> 3;
    const int b0     = cid * 4;
    const int h_base = rank * 64;
    const int kc     = tid >> 6;     // k-chunk 0..7 (64 k), 2 warps per chunk
    const int hl     = tid & 63;     // h-row within slice
    const float NSCALE = sqrtf(45.0f / 512.0f);

    // ---- mbarrier init + initial arm (expect 1024 B per source slice)
    if (tid == 0) {
#pragma unroll
        for (int bf = 0; bf < 2; bf++)
#pragma unroll
            for (int sc = 0; sc < 8; sc++) {
                if (sc == rank) continue;
                uint32_t m = smem_u32(&s->mbar[bf][sc]);
                asm volatile("mbarrier.init.shared.b64 [%0], 1;" :: "r"(m) : "memory");
                asm volatile("mbarrier.arrive.expect_tx.shared.b64 _, [%0], 1024;"
                             :: "r"(m) : "memory");
            }
        asm volatile("fence.mbarrier_init.release.cluster;" ::: "memory");
    }

    // ---- Wh slice -> registers: row (h_base+hl), cols [64kc, 64kc+64)
    ull w[32];
    {
        const ulonglong2* p = (const ulonglong2*)(Wh + (size_t)(h_base + hl) * HID + kc * 64);
#pragma unroll
        for (int j = 0; j < 16; j++) { ulonglong2 a = p[j]; w[2 * j] = a.x; w[2 * j + 1] = a.y; }
    }

    // ---- Wi slice -> SMEM (rows h_base..h_base+63, packed ull, pad 33)
    for (int i = tid; i < 64 * 32; i += 512) {
        int r = i >> 5, j = i & 31;
        s->wi[r][j] = ((const ull*)(Wi + (size_t)(h_base + r) * IN_DIM))[j];
    }
    // ---- rate0 -> buffer 0 (src-major layout), full 512 in every CTA
    for (int i = tid; i < 4 * HID; i += 512) {
        int b = i >> 9, h = i & 511;
        s->rate[0][h >> 6][b][h & 63] = rate0[(size_t)(b0 + b) * HID + h];
    }
    // ---- x[0] tile
    if (tid < 64) {
        int b = tid >> 4, k4 = tid & 15;
        float4 v = *(const float4*)(x + ((size_t)0 * BATCH + b0 + b) * IN_DIM + k4 * 4);
        ((float4*)&s->xbuf[0][b][0])[k4] = v;
    }
    __syncthreads();

    // ---- upper threads: compute pre[0] into prebuf[0]
    float bib = 0.f;
    int pb = 0, phh = 0;
    if (tid >= 256) {
        pb  = (tid - 256) >> 6;
        phh = tid & 63;
        int hg2 = h_base + phh;
        bib = bi[hg2] + bh[hg2];
        float n0 = noise[(size_t)(b0 + pb) * HID + hg2];
        ull acc = 0;
        const ulonglong2* xq = (const ulonglong2*)&s->xbuf[0][pb][0];
#pragma unroll
        for (int j = 0; j < 16; j++) {
            ulonglong2 xv = xq[j];
            FMA2(acc, s->wi[phh][2 * j], xv.x);
            FMA2(acc, s->wi[phh][2 * j + 1], xv.y);
        }
        s->prebuf[0][pb][phh] = hsum2(acc) + bib + NSCALE * n0;
    }
    __syncthreads();
    cluster_sync_();

    const int ub = tid >> 6;   // update batch (lower 256 threads)
    const int uh = tid & 63;
    const int hg = h_base + uh;

    // ---- peer SMEM bases (struct base mapped into each of the 7 peers)
    const uint32_t sbase = smem_u32(s);
    uint32_t peer_base[7];
#pragma unroll
    for (int i = 0; i < 7; i++)
        peer_base[i] = mapa_(sbase, (uint32_t)((rank + 1 + i) & 7));

    // byte offsets within RnnSmem (computed once)
    const uint32_t rate_off0 = (uint32_t)((char*)&s->rate[0][rank][ub][uh] - (char*)s);
    const uint32_t rate_off1 = (uint32_t)((char*)&s->rate[1][rank][ub][uh] - (char*)s);
    const uint32_t bar_off0  = (uint32_t)((char*)&s->mbar[0][rank] - (char*)s);
    const uint32_t bar_off1  = (uint32_t)((char*)&s->mbar[1][rank] - (char*)s);

    int ph0 = 0, ph1 = 0;      // wait parities for buffers 0/1

    for (int t = 0; t < T_STEPS; t++) {
        const int cur = t & 1, nxt = cur ^ 1;

        // ---- wait for this k-group's source slice (skip t=0 and own rank)
        if (t > 0 && kc != rank) {
            uint32_t bar = smem_u32(&s->mbar[cur][kc]);
            uint32_t par = cur ? (uint32_t)ph1 : (uint32_t)ph0;
            mbar_wait(bar, par);
            if ((tid & 63) == 0)
                asm volatile("mbarrier.arrive.expect_tx.shared.b64 _, [%0], 1024;"
                             :: "r"(bar) : "memory");
        }
        if (t > 0) { if (cur) ph1 ^= 1; else ph0 ^= 1; }

        // ---- prefetches for t+1 (overlapped with GEMM)
        float noise_next = 0.f;
        if (t < T_STEPS - 1) {
            if (tid < 64) {
                int b = tid >> 4, k4 = tid & 15;
                float4 v = *(const float4*)(x + ((size_t)(t + 1) * BATCH + b0 + b) * IN_DIM + k4 * 4);
                ((float4*)&s->xbuf[nxt][b][0])[k4] = v;
            }
            if (tid >= 256)
                noise_next = noise[((size_t)(t + 1) * BATCH + b0 + pb) * HID + h_base + phh];
        }

        // ---- f32x2 GEMM: 4 accumulators (1 h-row x 4 batches), 64-k chunk
        const ulonglong2* rb0 = (const ulonglong2*)&s->rate[cur][kc][0][0];
        const ulonglong2* rb1 = (const ulonglong2*)&s->rate[cur][kc][1][0];
        const ulonglong2* rb2 = (const ulonglong2*)&s->rate[cur][kc][2][0];
        const ulonglong2* rb3 = (const ulonglong2*)&s->rate[cur][kc][3][0];
        ull a0 = 0, a1 = 0, a2 = 0, a3 = 0;
#pragma unroll
        for (int q = 0; q < 16; q++) {
            ulonglong2 v0 = rb0[q], v1 = rb1[q], v2 = rb2[q], v3 = rb3[q];
            ull wa = w[2 * q], wb = w[2 * q + 1];
            FMA2(a0, wa, v0.x); FMA2(a1, wa, v1.x); FMA2(a2, wa, v2.x); FMA2(a3, wa, v3.x);
            FMA2(a0, wb, v0.y); FMA2(a1, wb, v1.y); FMA2(a2, wb, v2.y); FMA2(a3, wb, v3.y);
        }
        s->part[kc][0][hl] = hsum2(a0);
        s->part[kc][1][hl] = hsum2(a1);
        s->part[kc][2][hl] = hsum2(a2);
        s->part[kc][3][hl] = hsum2(a3);
        __syncthreads();

        if (tid < 256) {
            // ---- reduce + leaky tanh update for (ub, uh)
            float sum = ((s->part[0][ub][uh] + s->part[1][ub][uh])
                       + (s->part[2][ub][uh] + s->part[3][ub][uh]))
                      + ((s->part[4][ub][uh] + s->part[5][ub][uh])
                       + (s->part[6][ub][uh] + s->part[7][ub][uh]))
                      + s->prebuf[cur][ub][uh];
            float e, rc;
            asm("ex2.approx.f32 %0, %1;" : "=f"(e) : "f"(sum * 2.8853900817779268f));
            asm("rcp.approx.f32 %0, %1;" : "=f"(rc) : "f"(e + 1.0f));
            float th   = fmaf(-2.0f, rc, 1.0f);
            float prev = s->rate[cur][rank][ub][uh];
            float rnew = fmaf(0.9f, prev, 0.1f * th);

            // own slice locally; scatter to 7 peers with tx-completion
            s->rate[nxt][rank][ub][uh] = rnew;
            if (t < T_STEPS - 1) {
                uint32_t doff  = nxt ? rate_off1 : rate_off0;
                uint32_t boff  = nxt ? bar_off1  : bar_off0;
                uint32_t rbits = __float_as_uint(rnew);
#pragma unroll
                for (int p = 0; p < 7; p++)
                    asm volatile(
                        "st.async.weak.shared::cluster.mbarrier::complete_tx::bytes.b32 "
                        "[%0], %1, [%2];"
                        :: "r"(peer_base[p] + doff), "r"(rbits),
                           "r"(peer_base[p] + boff) : "memory");
            }
            rate_all[((size_t)t * BATCH + b0 + ub) * HID + hg] = rnew;
        } else if (t < T_STEPS - 1) {
            // ---- upper threads: pre[t+1] (overlapped with update)
            ull acc = 0;
            const ulonglong2* xq = (const ulonglong2*)&s->xbuf[nxt][pb][0];
#pragma unroll
            for (int j = 0; j < 16; j++) {
                ulonglong2 xv = xq[j];
                FMA2(acc, s->wi[phh][2 * j], xv.x);
                FMA2(acc, s->wi[phh][2 * j + 1], xv.y);
            }
            s->prebuf[nxt][pb][phh] = hsum2(acc) + bib + NSCALE * noise_next;
        }
        __syncthreads();
    }
    cluster_sync_();
}

// ---------------------------------------------------------------------------
// readout_kernel: unchanged.
// ---------------------------------------------------------------------------
__global__ void readout_kernel(const float* __restrict__ rate_all,
                               const float* __restrict__ Wo,
                               const float* __restrict__ bo,
                               const float* __restrict__ Woc,
                               const float* __restrict__ boc,
                               float* __restrict__ out,
                               float* __restrict__ outc) {
    __shared__ float4 rs[4][128];
    const int row0 = blockIdx.x * 4;
    const int tid  = threadIdx.x;   // 64

    const float4* r4 = (const float4*)(rate_all + (size_t)row0 * HID);
#pragma unroll
    for (int i = 0; i < 8; i++) {
        int idx = tid + 64 * i;
        rs[idx >> 7][idx & 127] = r4[idx];
    }
    __syncthreads();

    if (tid < O_DIM) {
        const float4* w4 = (const float4*)(Wo + (size_t)tid * HID);
        float b = bo[tid];
        float a[4] = {b, b, b, b};
#pragma unroll 4
        for (int k = 0; k < 128; k++) {
            float4 w = w4[k];
#pragma unroll
            for (int r = 0; r < 4; r++) {
                float4 v = rs[r][k];
                a[r] = fmaf(w.x, v.x, a[r]);
                a[r] = fmaf(w.y, v.y, a[r]);
                a[r] = fmaf(w.z, v.z, a[r]);
                a[r] = fmaf(w.w, v.w, a[r]);
            }
        }
#pragma unroll
        for (int r = 0; r < 4; r++)
            out[(size_t)(row0 + r) * O_DIM + tid] = a[r];
    } else if (tid < O_DIM + OC_DIM) {
        const int oc = tid - O_DIM;
        const float4* w4 = (const float4*)(Woc + (size_t)oc * HID);
        float b = boc[oc];
        float a[4] = {b, b, b, b};
#pragma unroll 4
        for (int k = 0; k < 128; k++) {
            float4 w = w4[k];
#pragma unroll
            for (int r = 0; r < 4; r++) {
                float4 v = rs[r][k];
                a[r] = fmaf(w.x, v.x, a[r]);
                a[r] = fmaf(w.y, v.y, a[r]);
                a[r] = fmaf(w.z, v.z, a[r]);
                a[r] = fmaf(w.w, v.w, a[r]);
            }
        }
#pragma unroll
        for (int r = 0; r < 4; r++)
            outc[(size_t)(row0 + r) * OC_DIM + oc] = a[r];
    }
}

// ---------------------------------------------------------------------------
extern "C" void kernel_launch(void* const* d_in, const int* in_sizes, int n_in,
                              void* d_out, int out_size) {
    const float* x     = (const float*)d_in[0];
    const float* rate0 = (const float*)d_in[1];
    const float* noise = (const float*)d_in[2];
    const float* Wi    = (const float*)d_in[3];
    const float* bi    = (const float*)d_in[4];
    const float* Wh    = (const float*)d_in[5];
    const float* bh    = (const float*)d_in[6];
    const float* Wo    = (const float*)d_in[7];
    const float* bo    = (const float*)d_in[8];
    const float* Woc   = (const float*)d_in[9];
    const float* boc   = (const float*)d_in[10];

    float* out      = (float*)d_out;
    float* outc     = out  + (size_t)T_STEPS * BATCH * O_DIM;
    float* rate_all = outc + (size_t)T_STEPS * BATCH * OC_DIM;

    cudaFuncSetAttribute(rnn_kernel, cudaFuncAttributeMaxDynamicSharedMemorySize,
                         (int)sizeof(RnnSmem));
    rnn_kernel<<<128, 512, sizeof(RnnSmem)>>>(x, rate0, noise, Wi, bi, Wh, bh, rate_all);

    readout_kernel<<<32768, 64>>>(rate_all, Wo, bo, Woc, boc, out, outc);
}